// round 3
// baseline (speedup 1.0000x reference)
#include <cuda_runtime.h>
#include <stdint.h>

#define NROWS 65536
#define KDIM  2048
#define BM 128
#define BK 32
#define NKT (KDIM / BK)   // 64

// ---------------- device scratch ----------------
__device__ int g_cnt[4];
__device__ int g_perm[4][NROWS];          // 1 MB
__device__ float g_W1tf[KDIM * 384];      // 3 MB: sc|st|wm|ch, tf32-rounded

#define W1OFF_SC 0
#define W1OFF_ST (KDIM * 64)
#define W1OFF_WM (KDIM * 128)
#define W1OFF_CH (KDIM * 256)

// ---------------- helpers ----------------
__device__ __forceinline__ void cp16(float* dst, const float* src) {
    uint32_t d = (uint32_t)__cvta_generic_to_shared(dst);
    asm volatile("cp.async.ca.shared.global [%0], [%1], 16;\n" :: "r"(d), "l"(src));
}
__device__ __forceinline__ uint32_t f2tf(float x) {
    uint32_t u; asm("cvt.rna.tf32.f32 %0, %1;" : "=r"(u) : "f"(x)); return u;
}

// ---------------- prep: tf32-round all W1s into g_W1tf ----------------
__global__ void prep_kernel(const float* __restrict__ W1_sc, const float* __restrict__ W1_st,
                            const float* __restrict__ W1_wm, const float* __restrict__ W1_ch) {
    const int T = KDIM * 384;
    for (int i = blockIdx.x * blockDim.x + threadIdx.x; i < T;
         i += gridDim.x * blockDim.x) {
        float v;
        if (i < W1OFF_ST)      v = W1_sc[i];
        else if (i < W1OFF_WM) v = W1_st[i - W1OFF_ST];
        else if (i < W1OFF_CH) v = W1_wm[i - W1OFF_WM];
        else                   v = W1_ch[i - W1OFF_CH];
        g_W1tf[i] = __uint_as_float(f2tf(v));
    }
}

// ---------------- bucket kernels ----------------
__global__ void zero_cnt_kernel() {
    if (threadIdx.x < 4) g_cnt[threadIdx.x] = 0;
}

__global__ void bucket_kernel(const int* __restrict__ labels, float* __restrict__ out) {
    int r = blockIdx.x * blockDim.x + threadIdx.x;
    if (r >= NROWS) return;
    int lab = labels[r];
    bool valid = (lab >= 0) && (lab <= 3);
    if (!valid) { out[r] = 0.f; lab = -1; }
    int lane = threadIdx.x & 31;
#pragma unroll
    for (int l = 0; l < 4; l++) {
        unsigned mask = __ballot_sync(0xffffffffu, lab == l);
        if (lab == l) {
            int leader = __ffs(mask) - 1;
            int myrank = __popc(mask & ((1u << lane) - 1));
            int basep = 0;
            if (lane == leader) basep = atomicAdd(&g_cnt[l], __popc(mask));
            basep = __shfl_sync(mask, basep, leader);
            g_perm[l][basep + myrank] = r;
        }
    }
}

// ---------------- fused expert body ----------------
template<int H>
__device__ __forceinline__ void expert_body(
    int e, int chunk, const float* __restrict__ X,
    const float* __restrict__ W1,   // tf32-rounded, [KDIM][H]
    const float* __restrict__ b1, const float* __restrict__ W2,
    const float* __restrict__ b2, const float* __restrict__ W3,
    const float* __restrict__ b3, float* __restrict__ out, float* smem)
{
    constexpr int H2  = H / 2;
    constexpr int JB  = H / 16;
    constexpr int JB2 = H2 / 16;

    int count = g_cnt[e];
    int base = chunk * BM;
    if (base >= count) return;
    const int* perm = g_perm[e];

    float* As    = smem;                    // 2*128*32
    float* Bs    = As + 2 * BM * BK;        // 2*32*H
    float* sW2   = Bs + 2 * BK * H;         // H*H2
    float* sW3   = sW2 + H * H2;            // H2
    float* sB2   = sW3 + H2;                // H2
    float* sPart = sB2 + H2;                // 128
    int*   sRow  = (int*)(sPart + 128);     // 128
    float* h1    = As;                      // reused post-mainloop (BM*H)

    int tid = threadIdx.x, lane = tid & 31, warp = tid >> 5;
    int wm = warp & 3, wn = warp >> 2;

    if (tid < BM) {
        int idx = base + tid;
        if (idx >= count) idx = count - 1;
        sRow[tid] = perm[idx];
    }
    for (int i = tid; i < H * H2; i += 256) {
        int k = i / H2, n = i - k * H2;
        sW2[k * H2 + (n ^ ((k & 3) << 3))] = __uint_as_float(f2tf(W2[i]));
    }
    if (tid < H2) { sW3[tid] = W3[tid]; sB2[tid] = b2[tid]; }
    __syncthreads();

    int rid[4];
#pragma unroll
    for (int it = 0; it < 4; it++) rid[it] = sRow[(tid + it * 256) >> 3];

    float acc[2][JB][4];
#pragma unroll
    for (int i = 0; i < 2; i++)
#pragma unroll
        for (int j = 0; j < JB; j++)
#pragma unroll
            for (int r = 0; r < 4; r++) acc[i][j][r] = 0.f;

    auto loadA = [&](int buf, int kt) {
        float* dst = As + buf * BM * BK;
#pragma unroll
        for (int it = 0; it < 4; it++) {
            int slot = tid + it * 256;
            int r  = slot >> 3;
            int c4 = (slot & 7) << 2;
            int pc = c4 ^ ((r & 7) << 2);
            cp16(dst + r * BK + pc, X + (size_t)rid[it] * KDIM + kt * BK + c4);
        }
    };
    auto loadB = [&](int buf, int kt) {
        float* dst = Bs + buf * BK * H;
        const float* src = W1 + (size_t)kt * BK * H;
#pragma unroll
        for (int it = 0; it < (BK * H) / 1024; it++) {
            int slot = tid + it * 256;
            int r  = slot / (H / 4);
            int c4 = (slot % (H / 4)) << 2;
            int pc = c4 ^ ((r & 3) << 3);
            cp16(dst + r * H + pc, src + r * H + c4);
        }
    };

    loadA(0, 0); loadB(0, 0);
    asm volatile("cp.async.commit_group;\n");

    for (int kt = 0; kt < NKT; kt++) {
        int buf = kt & 1;
        if (kt + 1 < NKT) {
            loadA(buf ^ 1, kt + 1);
            loadB(buf ^ 1, kt + 1);
            asm volatile("cp.async.commit_group;\n");
            asm volatile("cp.async.wait_group 1;\n");
        } else {
            asm volatile("cp.async.wait_group 0;\n");
        }
        __syncthreads();

        const float* A0 = As + buf * BM * BK;
        const float* B0 = Bs + buf * BK * H;

#pragma unroll
        for (int ks = 0; ks < 4; ks++) {
            uint32_t afr[2][4];
#pragma unroll
            for (int i = 0; i < 2; i++) {
                int row  = wm * 32 + i * 16 + (lane >> 2);
                int row8 = row + 8;
                int c0 = ks * 8 + (lane & 3);
                int c1 = c0 + 4;
                afr[i][0] = f2tf(A0[row  * BK + (c0 ^ ((row  & 7) << 2))]);
                afr[i][1] = f2tf(A0[row8 * BK + (c0 ^ ((row8 & 7) << 2))]);
                afr[i][2] = f2tf(A0[row  * BK + (c1 ^ ((row  & 7) << 2))]);
                afr[i][3] = f2tf(A0[row8 * BK + (c1 ^ ((row8 & 7) << 2))]);
            }
            uint32_t bfr[JB][2];
#pragma unroll
            for (int j = 0; j < JB; j++) {
                int n  = wn * (H / 2) + j * 8 + (lane >> 2);
                int k0 = ks * 8 + (lane & 3);
                int k1 = k0 + 4;
                bfr[j][0] = __float_as_uint(B0[k0 * H + (n ^ ((k0 & 3) << 3))]);
                bfr[j][1] = __float_as_uint(B0[k1 * H + (n ^ ((k1 & 3) << 3))]);
            }
#pragma unroll
            for (int i = 0; i < 2; i++)
#pragma unroll
                for (int j = 0; j < JB; j++) {
                    asm volatile(
                        "mma.sync.aligned.m16n8k8.row.col.f32.tf32.tf32.f32 "
                        "{%0,%1,%2,%3}, {%4,%5,%6,%7}, {%8,%9}, {%0,%1,%2,%3};\n"
                        : "+f"(acc[i][j][0]), "+f"(acc[i][j][1]),
                          "+f"(acc[i][j][2]), "+f"(acc[i][j][3])
                        : "r"(afr[i][0]), "r"(afr[i][1]), "r"(afr[i][2]), "r"(afr[i][3]),
                          "r"(bfr[j][0]), "r"(bfr[j][1]));
                }
        }
        __syncthreads();
    }

    // ---- layer-1 epilogue: +b1, relu, tf32-round, store h1 (swizzled) ----
#pragma unroll
    for (int i = 0; i < 2; i++) {
        int row0 = wm * 32 + i * 16 + (lane >> 2);
        int row1 = row0 + 8;
#pragma unroll
        for (int j = 0; j < JB; j++) {
            int col = wn * (H / 2) + j * 8 + 2 * (lane & 3);
            float bv0 = b1[col], bv1 = b1[col + 1];
            h1[row0 * H + ((col)     ^ ((row0 & 7) << 2))] =
                __uint_as_float(f2tf(fmaxf(acc[i][j][0] + bv0, 0.f)));
            h1[row0 * H + ((col + 1) ^ ((row0 & 7) << 2))] =
                __uint_as_float(f2tf(fmaxf(acc[i][j][1] + bv1, 0.f)));
            h1[row1 * H + ((col)     ^ ((row1 & 7) << 2))] =
                __uint_as_float(f2tf(fmaxf(acc[i][j][2] + bv0, 0.f)));
            h1[row1 * H + ((col + 1) ^ ((row1 & 7) << 2))] =
                __uint_as_float(f2tf(fmaxf(acc[i][j][3] + bv1, 0.f)));
        }
    }
    __syncthreads();

    // ---- layer 2: acc2 = h1 @ W2 (tf32 mma; both operands pre-rounded) ----
    float acc2[2][JB2][4];
#pragma unroll
    for (int i = 0; i < 2; i++)
#pragma unroll
        for (int j = 0; j < JB2; j++)
#pragma unroll
            for (int r = 0; r < 4; r++) acc2[i][j][r] = 0.f;

#pragma unroll
    for (int ks = 0; ks < H / 8; ks++) {
        uint32_t afr[2][4];
#pragma unroll
        for (int i = 0; i < 2; i++) {
            int row  = wm * 32 + i * 16 + (lane >> 2);
            int row8 = row + 8;
            int c0 = ks * 8 + (lane & 3);
            int c1 = c0 + 4;
            afr[i][0] = __float_as_uint(h1[row  * H + (c0 ^ ((row  & 7) << 2))]);
            afr[i][1] = __float_as_uint(h1[row8 * H + (c0 ^ ((row8 & 7) << 2))]);
            afr[i][2] = __float_as_uint(h1[row  * H + (c1 ^ ((row  & 7) << 2))]);
            afr[i][3] = __float_as_uint(h1[row8 * H + (c1 ^ ((row8 & 7) << 2))]);
        }
        uint32_t bfr[JB2][2];
#pragma unroll
        for (int j = 0; j < JB2; j++) {
            int n  = wn * (H2 / 2) + j * 8 + (lane >> 2);
            int k0 = ks * 8 + (lane & 3);
            int k1 = k0 + 4;
            bfr[j][0] = __float_as_uint(sW2[k0 * H2 + (n ^ ((k0 & 3) << 3))]);
            bfr[j][1] = __float_as_uint(sW2[k1 * H2 + (n ^ ((k1 & 3) << 3))]);
        }
#pragma unroll
        for (int i = 0; i < 2; i++)
#pragma unroll
            for (int j = 0; j < JB2; j++) {
                asm volatile(
                    "mma.sync.aligned.m16n8k8.row.col.f32.tf32.tf32.f32 "
                    "{%0,%1,%2,%3}, {%4,%5,%6,%7}, {%8,%9}, {%0,%1,%2,%3};\n"
                    : "+f"(acc2[i][j][0]), "+f"(acc2[i][j][1]),
                      "+f"(acc2[i][j][2]), "+f"(acc2[i][j][3])
                    : "r"(afr[i][0]), "r"(afr[i][1]), "r"(afr[i][2]), "r"(afr[i][3]),
                      "r"(bfr[j][0]), "r"(bfr[j][1]));
            }
    }

    // ---- layer 3: +b2, relu, dot W3, reduce, +b3, scatter ----
    float p[4] = {0.f, 0.f, 0.f, 0.f};
#pragma unroll
    for (int i = 0; i < 2; i++)
#pragma unroll
        for (int j = 0; j < JB2; j++) {
            int col = wn * (H2 / 2) + j * 8 + 2 * (lane & 3);
            float w0 = sW3[col], w1 = sW3[col + 1];
            float c0 = sB2[col], c1 = sB2[col + 1];
            p[i * 2 + 0] += fmaxf(acc2[i][j][0] + c0, 0.f) * w0
                          + fmaxf(acc2[i][j][1] + c1, 0.f) * w1;
            p[i * 2 + 1] += fmaxf(acc2[i][j][2] + c0, 0.f) * w0
                          + fmaxf(acc2[i][j][3] + c1, 0.f) * w1;
        }
#pragma unroll
    for (int t = 0; t < 4; t++) {
        p[t] += __shfl_xor_sync(0xffffffffu, p[t], 1);
        p[t] += __shfl_xor_sync(0xffffffffu, p[t], 2);
    }
    if (wn == 0 && (lane & 3) == 0) {
#pragma unroll
        for (int i = 0; i < 2; i++)
#pragma unroll
            for (int hh = 0; hh < 2; hh++) {
                int m = wm * 32 + i * 16 + hh * 8 + (lane >> 2);
                sPart[m] = p[i * 2 + hh];
            }
    }
    __syncthreads();
    if (wn == 1 && (lane & 3) == 0) {
        float b3v = b3[0];
#pragma unroll
        for (int i = 0; i < 2; i++)
#pragma unroll
            for (int hh = 0; hh < 2; hh++) {
                int m = wm * 32 + i * 16 + hh * 8 + (lane >> 2);
                if (base + m < count)
                    out[sRow[m]] = sPart[m] + p[i * 2 + hh] + b3v;
            }
    }
}

// ---------------- fused kernel: all 4 experts in one launch ----------------
__global__ __launch_bounds__(256, 2) void fused_kernel(
    const float* __restrict__ X,
    const float* __restrict__ b1_sc, const float* __restrict__ W2_sc,
    const float* __restrict__ b2_sc, const float* __restrict__ W3_sc,
    const float* __restrict__ b3_sc,
    const float* __restrict__ b1_st, const float* __restrict__ W2_st,
    const float* __restrict__ b2_st, const float* __restrict__ W3_st,
    const float* __restrict__ b3_st,
    const float* __restrict__ b1_wm, const float* __restrict__ W2_wm,
    const float* __restrict__ b2_wm, const float* __restrict__ W3_wm,
    const float* __restrict__ b3_wm,
    const float* __restrict__ b1_ch, const float* __restrict__ W2_ch,
    const float* __restrict__ b2_ch, const float* __restrict__ W3_ch,
    const float* __restrict__ b3_ch,
    float* __restrict__ out)
{
    extern __shared__ float smem[];
    int e = blockIdx.x & 3;        // interleave experts for load balance
    int chunk = blockIdx.x >> 2;
    if (e == 0)
        expert_body<64>(0, chunk, X, g_W1tf + W1OFF_SC,
                        b1_sc, W2_sc, b2_sc, W3_sc, b3_sc, out, smem);
    else if (e == 1)
        expert_body<64>(1, chunk, X, g_W1tf + W1OFF_ST,
                        b1_st, W2_st, b2_st, W3_st, b3_st, out, smem);
    else if (e == 2)
        expert_body<128>(2, chunk, X, g_W1tf + W1OFF_WM,
                         b1_wm, W2_wm, b2_wm, W3_wm, b3_wm, out, smem);
    else
        expert_body<128>(3, chunk, X, g_W1tf + W1OFF_CH,
                         b1_ch, W2_ch, b2_ch, W3_ch, b3_ch, out, smem);
}

// ---------------- launch ----------------
extern "C" void kernel_launch(void* const* d_in, const int* in_sizes, int n_in,
                              void* d_out, int out_size) {
    const float* x      = (const float*)d_in[0];
    const int*   labels = (const int*)d_in[1];
    const float* W1_sc = (const float*)d_in[2],  *b1_sc = (const float*)d_in[3];
    const float* W2_sc = (const float*)d_in[4],  *b2_sc = (const float*)d_in[5];
    const float* W3_sc = (const float*)d_in[6],  *b3_sc = (const float*)d_in[7];
    const float* W1_st = (const float*)d_in[8],  *b1_st = (const float*)d_in[9];
    const float* W2_st = (const float*)d_in[10], *b2_st = (const float*)d_in[11];
    const float* W3_st = (const float*)d_in[12], *b3_st = (const float*)d_in[13];
    const float* W1_wm = (const float*)d_in[14], *b1_wm = (const float*)d_in[15];
    const float* W2_wm = (const float*)d_in[16], *b2_wm = (const float*)d_in[17];
    const float* W3_wm = (const float*)d_in[18], *b3_wm = (const float*)d_in[19];
    const float* W1_ch = (const float*)d_in[20], *b1_ch = (const float*)d_in[21];
    const float* W2_ch = (const float*)d_in[22], *b2_ch = (const float*)d_in[23];
    const float* W3_ch = (const float*)d_in[24], *b3_ch = (const float*)d_in[25];
    float* out = (float*)d_out;

    zero_cnt_kernel<<<1, 32>>>();
    bucket_kernel<<<NROWS / 256, 256>>>(labels, out);
    prep_kernel<<<768, 256>>>(W1_sc, W1_st, W1_wm, W1_ch);

    // smem (floats), H=128 layout is the max:
    // 8192 (A) + 8192 (B) + 8192 (W2) + 64 + 64 + 128 + 128 = 24960 -> 99840 B
    const size_t smem_max = 24960 * sizeof(float);
    cudaFuncSetAttribute(fused_kernel, cudaFuncAttributeMaxDynamicSharedMemorySize,
                         (int)smem_max);

    fused_kernel<<<4 * (NROWS / BM), 256, smem_max>>>(x,
        b1_sc, W2_sc, b2_sc, W3_sc, b3_sc,
        b1_st, W2_st, b2_st, W3_st, b3_st,
        b1_wm, W2_wm, b2_wm, W3_wm, b3_wm,
        b1_ch, W2_ch, b2_ch, W3_ch, b3_ch,
        out);
}

// round 4
// speedup vs baseline: 1.0032x; 1.0032x over previous
#include <cuda_runtime.h>
#include <stdint.h>

#define NROWS 65536
#define KDIM  2048
#define BM 128
#define BK 32
#define NKT (KDIM / BK)   // 64

// ---------------- device scratch ----------------
__device__ int g_cnt[4];
__device__ int g_perm[4][NROWS];          // 1 MB
__device__ float g_W1tf[KDIM * 384];      // 3 MB: sc|st|wm|ch, tf32-rounded

#define W1OFF_SC 0
#define W1OFF_ST (KDIM * 64)
#define W1OFF_WM (KDIM * 128)
#define W1OFF_CH (KDIM * 256)

// ---------------- helpers ----------------
__device__ __forceinline__ void cp16(float* dst, const float* src) {
    uint32_t d = (uint32_t)__cvta_generic_to_shared(dst);
    asm volatile("cp.async.ca.shared.global [%0], [%1], 16;\n" :: "r"(d), "l"(src));
}
__device__ __forceinline__ uint32_t f2tf(float x) {
    uint32_t u; asm("cvt.rna.tf32.f32 %0, %1;" : "=r"(u) : "f"(x)); return u;
}

// ---------------- prep: tf32-round all W1s into g_W1tf ----------------
__global__ void prep_kernel(const float* __restrict__ W1_sc, const float* __restrict__ W1_st,
                            const float* __restrict__ W1_wm, const float* __restrict__ W1_ch) {
    const int T = KDIM * 384;
    for (int i = blockIdx.x * blockDim.x + threadIdx.x; i < T;
         i += gridDim.x * blockDim.x) {
        float v;
        if (i < W1OFF_ST)      v = W1_sc[i];
        else if (i < W1OFF_WM) v = W1_st[i - W1OFF_ST];
        else if (i < W1OFF_CH) v = W1_wm[i - W1OFF_WM];
        else                   v = W1_ch[i - W1OFF_CH];
        g_W1tf[i] = __uint_as_float(f2tf(v));
    }
}

// ---------------- bucket kernels ----------------
__global__ void zero_cnt_kernel() {
    if (threadIdx.x < 4) g_cnt[threadIdx.x] = 0;
}

__global__ void bucket_kernel(const int* __restrict__ labels, float* __restrict__ out) {
    int r = blockIdx.x * blockDim.x + threadIdx.x;
    if (r >= NROWS) return;
    int lab = labels[r];
    bool valid = (lab >= 0) && (lab <= 3);
    if (!valid) { out[r] = 0.f; lab = -1; }
    int lane = threadIdx.x & 31;
#pragma unroll
    for (int l = 0; l < 4; l++) {
        unsigned mask = __ballot_sync(0xffffffffu, lab == l);
        if (lab == l) {
            int leader = __ffs(mask) - 1;
            int myrank = __popc(mask & ((1u << lane) - 1));
            int basep = 0;
            if (lane == leader) basep = atomicAdd(&g_cnt[l], __popc(mask));
            basep = __shfl_sync(mask, basep, leader);
            g_perm[l][basep + myrank] = r;
        }
    }
}

// ---------------- fused expert body ----------------
template<int H>
__device__ __forceinline__ void expert_body(
    int e, int chunk, const float* __restrict__ X,
    const float* __restrict__ W1,   // tf32-rounded, [KDIM][H]
    const float* __restrict__ b1, const float* __restrict__ W2,
    const float* __restrict__ b2, const float* __restrict__ W3,
    const float* __restrict__ b3, float* __restrict__ out, float* smem)
{
    constexpr int H2  = H / 2;
    constexpr int JB  = H / 16;
    constexpr int JB2 = H2 / 16;

    int count = g_cnt[e];
    int base = chunk * BM;
    if (base >= count) return;
    const int* perm = g_perm[e];

    float* As    = smem;                    // 2*128*32
    float* Bs    = As + 2 * BM * BK;        // 2*32*H
    float* sW2   = Bs + 2 * BK * H;         // H*H2
    float* sW3   = sW2 + H * H2;            // H2
    float* sB2   = sW3 + H2;                // H2
    float* sPart = sB2 + H2;                // 128
    int*   sRow  = (int*)(sPart + 128);     // 128
    float* h1    = As;                      // reused post-mainloop (BM*H)

    int tid = threadIdx.x, lane = tid & 31, warp = tid >> 5;
    int wm = warp & 3, wn = warp >> 2;

    if (tid < BM) {
        int idx = base + tid;
        if (idx >= count) idx = count - 1;
        sRow[tid] = perm[idx];
    }
    for (int i = tid; i < H * H2; i += 256) {
        int k = i / H2, n = i - k * H2;
        sW2[k * H2 + (n ^ ((k & 3) << 3))] = __uint_as_float(f2tf(W2[i]));
    }
    if (tid < H2) { sW3[tid] = W3[tid]; sB2[tid] = b2[tid]; }
    __syncthreads();

    int rid[4];
#pragma unroll
    for (int it = 0; it < 4; it++) rid[it] = sRow[(tid + it * 256) >> 3];

    float acc[2][JB][4];
#pragma unroll
    for (int i = 0; i < 2; i++)
#pragma unroll
        for (int j = 0; j < JB; j++)
#pragma unroll
            for (int r = 0; r < 4; r++) acc[i][j][r] = 0.f;

    auto loadA = [&](int buf, int kt) {
        float* dst = As + buf * BM * BK;
#pragma unroll
        for (int it = 0; it < 4; it++) {
            int slot = tid + it * 256;
            int r  = slot >> 3;
            int c4 = (slot & 7) << 2;
            int pc = c4 ^ ((r & 7) << 2);
            cp16(dst + r * BK + pc, X + (size_t)rid[it] * KDIM + kt * BK + c4);
        }
    };
    auto loadB = [&](int buf, int kt) {
        float* dst = Bs + buf * BK * H;
        const float* src = W1 + (size_t)kt * BK * H;
#pragma unroll
        for (int it = 0; it < (BK * H) / 1024; it++) {
            int slot = tid + it * 256;
            int r  = slot / (H / 4);
            int c4 = (slot % (H / 4)) << 2;
            int pc = c4 ^ ((r & 3) << 3);
            cp16(dst + r * H + pc, src + r * H + c4);
        }
    };

    loadA(0, 0); loadB(0, 0);
    asm volatile("cp.async.commit_group;\n");

    for (int kt = 0; kt < NKT; kt++) {
        int buf = kt & 1;
        if (kt + 1 < NKT) {
            loadA(buf ^ 1, kt + 1);
            loadB(buf ^ 1, kt + 1);
            asm volatile("cp.async.commit_group;\n");
            asm volatile("cp.async.wait_group 1;\n");
        } else {
            asm volatile("cp.async.wait_group 0;\n");
        }
        __syncthreads();

        const float* A0 = As + buf * BM * BK;
        const float* B0 = Bs + buf * BK * H;

#pragma unroll
        for (int ks = 0; ks < 4; ks++) {
            uint32_t afr[2][4];
#pragma unroll
            for (int i = 0; i < 2; i++) {
                int row  = wm * 32 + i * 16 + (lane >> 2);
                int row8 = row + 8;
                int c0 = ks * 8 + (lane & 3);
                int c1 = c0 + 4;
                afr[i][0] = f2tf(A0[row  * BK + (c0 ^ ((row  & 7) << 2))]);
                afr[i][1] = f2tf(A0[row8 * BK + (c0 ^ ((row8 & 7) << 2))]);
                afr[i][2] = f2tf(A0[row  * BK + (c1 ^ ((row  & 7) << 2))]);
                afr[i][3] = f2tf(A0[row8 * BK + (c1 ^ ((row8 & 7) << 2))]);
            }
            uint32_t bfr[JB][2];
#pragma unroll
            for (int j = 0; j < JB; j++) {
                int n  = wn * (H / 2) + j * 8 + (lane >> 2);
                int k0 = ks * 8 + (lane & 3);
                int k1 = k0 + 4;
                bfr[j][0] = __float_as_uint(B0[k0 * H + (n ^ ((k0 & 3) << 3))]);
                bfr[j][1] = __float_as_uint(B0[k1 * H + (n ^ ((k1 & 3) << 3))]);
            }
#pragma unroll
            for (int i = 0; i < 2; i++)
#pragma unroll
                for (int j = 0; j < JB; j++) {
                    asm volatile(
                        "mma.sync.aligned.m16n8k8.row.col.f32.tf32.tf32.f32 "
                        "{%0,%1,%2,%3}, {%4,%5,%6,%7}, {%8,%9}, {%0,%1,%2,%3};\n"
                        : "+f"(acc[i][j][0]), "+f"(acc[i][j][1]),
                          "+f"(acc[i][j][2]), "+f"(acc[i][j][3])
                        : "r"(afr[i][0]), "r"(afr[i][1]), "r"(afr[i][2]), "r"(afr[i][3]),
                          "r"(bfr[j][0]), "r"(bfr[j][1]));
                }
        }
        __syncthreads();
    }

    // ---- layer-1 epilogue: +b1, relu, tf32-round, store h1 (swizzled) ----
#pragma unroll
    for (int i = 0; i < 2; i++) {
        int row0 = wm * 32 + i * 16 + (lane >> 2);
        int row1 = row0 + 8;
#pragma unroll
        for (int j = 0; j < JB; j++) {
            int col = wn * (H / 2) + j * 8 + 2 * (lane & 3);
            float bv0 = b1[col], bv1 = b1[col + 1];
            h1[row0 * H + ((col)     ^ ((row0 & 7) << 2))] =
                __uint_as_float(f2tf(fmaxf(acc[i][j][0] + bv0, 0.f)));
            h1[row0 * H + ((col + 1) ^ ((row0 & 7) << 2))] =
                __uint_as_float(f2tf(fmaxf(acc[i][j][1] + bv1, 0.f)));
            h1[row1 * H + ((col)     ^ ((row1 & 7) << 2))] =
                __uint_as_float(f2tf(fmaxf(acc[i][j][2] + bv0, 0.f)));
            h1[row1 * H + ((col + 1) ^ ((row1 & 7) << 2))] =
                __uint_as_float(f2tf(fmaxf(acc[i][j][3] + bv1, 0.f)));
        }
    }
    __syncthreads();

    // ---- layer 2: acc2 = h1 @ W2 (tf32 mma; both operands pre-rounded) ----
    float acc2[2][JB2][4];
#pragma unroll
    for (int i = 0; i < 2; i++)
#pragma unroll
        for (int j = 0; j < JB2; j++)
#pragma unroll
            for (int r = 0; r < 4; r++) acc2[i][j][r] = 0.f;

#pragma unroll
    for (int ks = 0; ks < H / 8; ks++) {
        uint32_t afr[2][4];
#pragma unroll
        for (int i = 0; i < 2; i++) {
            int row  = wm * 32 + i * 16 + (lane >> 2);
            int row8 = row + 8;
            int c0 = ks * 8 + (lane & 3);
            int c1 = c0 + 4;
            afr[i][0] = __float_as_uint(h1[row  * H + (c0 ^ ((row  & 7) << 2))]);
            afr[i][1] = __float_as_uint(h1[row8 * H + (c0 ^ ((row8 & 7) << 2))]);
            afr[i][2] = __float_as_uint(h1[row  * H + (c1 ^ ((row  & 7) << 2))]);
            afr[i][3] = __float_as_uint(h1[row8 * H + (c1 ^ ((row8 & 7) << 2))]);
        }
        uint32_t bfr[JB2][2];
#pragma unroll
        for (int j = 0; j < JB2; j++) {
            int n  = wn * (H2 / 2) + j * 8 + (lane >> 2);
            int k0 = ks * 8 + (lane & 3);
            int k1 = k0 + 4;
            bfr[j][0] = __float_as_uint(sW2[k0 * H2 + (n ^ ((k0 & 3) << 3))]);
            bfr[j][1] = __float_as_uint(sW2[k1 * H2 + (n ^ ((k1 & 3) << 3))]);
        }
#pragma unroll
        for (int i = 0; i < 2; i++)
#pragma unroll
            for (int j = 0; j < JB2; j++) {
                asm volatile(
                    "mma.sync.aligned.m16n8k8.row.col.f32.tf32.tf32.f32 "
                    "{%0,%1,%2,%3}, {%4,%5,%6,%7}, {%8,%9}, {%0,%1,%2,%3};\n"
                    : "+f"(acc2[i][j][0]), "+f"(acc2[i][j][1]),
                      "+f"(acc2[i][j][2]), "+f"(acc2[i][j][3])
                    : "r"(afr[i][0]), "r"(afr[i][1]), "r"(afr[i][2]), "r"(afr[i][3]),
                      "r"(bfr[j][0]), "r"(bfr[j][1]));
            }
    }

    // ---- layer 3: +b2, relu, dot W3, reduce, +b3, scatter ----
    float p[4] = {0.f, 0.f, 0.f, 0.f};
#pragma unroll
    for (int i = 0; i < 2; i++)
#pragma unroll
        for (int j = 0; j < JB2; j++) {
            int col = wn * (H2 / 2) + j * 8 + 2 * (lane & 3);
            float w0 = sW3[col], w1 = sW3[col + 1];
            float c0 = sB2[col], c1 = sB2[col + 1];
            p[i * 2 + 0] += fmaxf(acc2[i][j][0] + c0, 0.f) * w0
                          + fmaxf(acc2[i][j][1] + c1, 0.f) * w1;
            p[i * 2 + 1] += fmaxf(acc2[i][j][2] + c0, 0.f) * w0
                          + fmaxf(acc2[i][j][3] + c1, 0.f) * w1;
        }
#pragma unroll
    for (int t = 0; t < 4; t++) {
        p[t] += __shfl_xor_sync(0xffffffffu, p[t], 1);
        p[t] += __shfl_xor_sync(0xffffffffu, p[t], 2);
    }
    if (wn == 0 && (lane & 3) == 0) {
#pragma unroll
        for (int i = 0; i < 2; i++)
#pragma unroll
            for (int hh = 0; hh < 2; hh++) {
                int m = wm * 32 + i * 16 + hh * 8 + (lane >> 2);
                sPart[m] = p[i * 2 + hh];
            }
    }
    __syncthreads();
    if (wn == 1 && (lane & 3) == 0) {
        float b3v = b3[0];
#pragma unroll
        for (int i = 0; i < 2; i++)
#pragma unroll
            for (int hh = 0; hh < 2; hh++) {
                int m = wm * 32 + i * 16 + hh * 8 + (lane >> 2);
                if (base + m < count)
                    out[sRow[m]] = sPart[m] + p[i * 2 + hh] + b3v;
            }
    }
}

// ---------------- fused kernel: all 4 experts in one launch ----------------
__global__ __launch_bounds__(256, 2) void fused_kernel(
    const float* __restrict__ X,
    const float* __restrict__ b1_sc, const float* __restrict__ W2_sc,
    const float* __restrict__ b2_sc, const float* __restrict__ W3_sc,
    const float* __restrict__ b3_sc,
    const float* __restrict__ b1_st, const float* __restrict__ W2_st,
    const float* __restrict__ b2_st, const float* __restrict__ W3_st,
    const float* __restrict__ b3_st,
    const float* __restrict__ b1_wm, const float* __restrict__ W2_wm,
    const float* __restrict__ b2_wm, const float* __restrict__ W3_wm,
    const float* __restrict__ b3_wm,
    const float* __restrict__ b1_ch, const float* __restrict__ W2_ch,
    const float* __restrict__ b2_ch, const float* __restrict__ W3_ch,
    const float* __restrict__ b3_ch,
    float* __restrict__ out)
{
    extern __shared__ float smem[];
    int e = blockIdx.x & 3;        // interleave experts for load balance
    int chunk = blockIdx.x >> 2;
    if (e == 0)
        expert_body<64>(0, chunk, X, g_W1tf + W1OFF_SC,
                        b1_sc, W2_sc, b2_sc, W3_sc, b3_sc, out, smem);
    else if (e == 1)
        expert_body<64>(1, chunk, X, g_W1tf + W1OFF_ST,
                        b1_st, W2_st, b2_st, W3_st, b3_st, out, smem);
    else if (e == 2)
        expert_body<128>(2, chunk, X, g_W1tf + W1OFF_WM,
                         b1_wm, W2_wm, b2_wm, W3_wm, b3_wm, out, smem);
    else
        expert_body<128>(3, chunk, X, g_W1tf + W1OFF_CH,
                         b1_ch, W2_ch, b2_ch, W3_ch, b3_ch, out, smem);
}

// ---------------- launch ----------------
extern "C" void kernel_launch(void* const* d_in, const int* in_sizes, int n_in,
                              void* d_out, int out_size) {
    const float* x      = (const float*)d_in[0];
    const int*   labels = (const int*)d_in[1];
    const float* W1_sc = (const float*)d_in[2],  *b1_sc = (const float*)d_in[3];
    const float* W2_sc = (const float*)d_in[4],  *b2_sc = (const float*)d_in[5];
    const float* W3_sc = (const float*)d_in[6],  *b3_sc = (const float*)d_in[7];
    const float* W1_st = (const float*)d_in[8],  *b1_st = (const float*)d_in[9];
    const float* W2_st = (const float*)d_in[10], *b2_st = (const float*)d_in[11];
    const float* W3_st = (const float*)d_in[12], *b3_st = (const float*)d_in[13];
    const float* W1_wm = (const float*)d_in[14], *b1_wm = (const float*)d_in[15];
    const float* W2_wm = (const float*)d_in[16], *b2_wm = (const float*)d_in[17];
    const float* W3_wm = (const float*)d_in[18], *b3_wm = (const float*)d_in[19];
    const float* W1_ch = (const float*)d_in[20], *b1_ch = (const float*)d_in[21];
    const float* W2_ch = (const float*)d_in[22], *b2_ch = (const float*)d_in[23];
    const float* W3_ch = (const float*)d_in[24], *b3_ch = (const float*)d_in[25];
    float* out = (float*)d_out;

    zero_cnt_kernel<<<1, 32>>>();
    bucket_kernel<<<NROWS / 256, 256>>>(labels, out);
    prep_kernel<<<768, 256>>>(W1_sc, W1_st, W1_wm, W1_ch);

    // smem (floats), H=128 layout is the max:
    // 8192 (A) + 8192 (B) + 8192 (W2) + 64 + 64 + 128 + 128 = 24960 -> 99840 B
    const size_t smem_max = 24960 * sizeof(float);
    cudaFuncSetAttribute(fused_kernel, cudaFuncAttributeMaxDynamicSharedMemorySize,
                         (int)smem_max);

    fused_kernel<<<4 * (NROWS / BM), 256, smem_max>>>(x,
        b1_sc, W2_sc, b2_sc, W3_sc, b3_sc,
        b1_st, W2_st, b2_st, W3_st, b3_st,
        b1_wm, W2_wm, b2_wm, W3_wm, b3_wm,
        b1_ch, W2_ch, b2_ch, W3_ch, b3_ch,
        out);
}

// round 5
// speedup vs baseline: 1.1034x; 1.0999x over previous
#include <cuda_runtime.h>
#include <stdint.h>

#define NROWS 65536
#define KDIM  2048
#define BM 128
#define BK 32
#define NKT (KDIM / BK)   // 64
#define NTHREADS 512

// ---------------- device scratch ----------------
__device__ int g_cnt[4];
__device__ int g_perm[4][NROWS];          // 1 MB
__device__ float g_W1tf[KDIM * 384];      // 3 MB: sc|st|wm|ch, tf32-rounded

#define W1OFF_SC 0
#define W1OFF_ST (KDIM * 64)
#define W1OFF_WM (KDIM * 128)
#define W1OFF_CH (KDIM * 256)

// ---------------- helpers ----------------
__device__ __forceinline__ void cp16(float* dst, const float* src) {
    uint32_t d = (uint32_t)__cvta_generic_to_shared(dst);
    asm volatile("cp.async.ca.shared.global [%0], [%1], 16;\n" :: "r"(d), "l"(src));
}
__device__ __forceinline__ uint32_t f2tf(float x) {
    uint32_t u; asm("cvt.rna.tf32.f32 %0, %1;" : "=r"(u) : "f"(x)); return u;
}

// ---------------- prep: tf32-round all W1s into g_W1tf ----------------
__global__ void prep_kernel(const float* __restrict__ W1_sc, const float* __restrict__ W1_st,
                            const float* __restrict__ W1_wm, const float* __restrict__ W1_ch) {
    const int T = KDIM * 384;
    for (int i = blockIdx.x * blockDim.x + threadIdx.x; i < T;
         i += gridDim.x * blockDim.x) {
        float v;
        if (i < W1OFF_ST)      v = W1_sc[i];
        else if (i < W1OFF_WM) v = W1_st[i - W1OFF_ST];
        else if (i < W1OFF_CH) v = W1_wm[i - W1OFF_WM];
        else                   v = W1_ch[i - W1OFF_CH];
        g_W1tf[i] = __uint_as_float(f2tf(v));
    }
}

// ---------------- bucket kernels ----------------
__global__ void zero_cnt_kernel() {
    if (threadIdx.x < 4) g_cnt[threadIdx.x] = 0;
}

__global__ void bucket_kernel(const int* __restrict__ labels, float* __restrict__ out) {
    int r = blockIdx.x * blockDim.x + threadIdx.x;
    if (r >= NROWS) return;
    int lab = labels[r];
    bool valid = (lab >= 0) && (lab <= 3);
    if (!valid) { out[r] = 0.f; lab = -1; }
    int lane = threadIdx.x & 31;
#pragma unroll
    for (int l = 0; l < 4; l++) {
        unsigned mask = __ballot_sync(0xffffffffu, lab == l);
        if (lab == l) {
            int leader = __ffs(mask) - 1;
            int myrank = __popc(mask & ((1u << lane) - 1));
            int basep = 0;
            if (lane == leader) basep = atomicAdd(&g_cnt[l], __popc(mask));
            basep = __shfl_sync(mask, basep, leader);
            g_perm[l][basep + myrank] = r;
        }
    }
}

// ---------------- fused expert body (512 threads, 16 warps = 4m x 4n) ----------------
template<int H>
__device__ __forceinline__ void expert_body(
    int e, int chunk, const float* __restrict__ X,
    const float* __restrict__ W1,   // tf32-rounded [KDIM][H]
    const float* __restrict__ b1, const float* __restrict__ W2,
    const float* __restrict__ b2, const float* __restrict__ W3,
    const float* __restrict__ b3, float* __restrict__ out, float* smem)
{
    constexpr int H2  = H / 2;
    constexpr int JB  = H / 32;    // layer-1 n8 blocks per warp (warp n-tile H/4)
    constexpr int JB2 = H2 / 32;   // layer-2 n8 blocks per warp (warp n-tile H2/4)

    int count = g_cnt[e];
    int base = chunk * BM;
    if (base >= count) return;
    const int* perm = g_perm[e];

    float* As    = smem;                    // 3*128*32 = 12288
    float* Bs    = As + 3 * BM * BK;        // 3*32*H
    float* sW2   = Bs + 3 * BK * H;         // H*H2
    float* sW3   = sW2 + H * H2;            // H2
    float* sB2   = sW3 + H2;                // H2
    float* sPart = sB2 + H2;                // 128
    int*   sRow  = (int*)(sPart + 128);     // 128
    float* h1    = As;                      // reused post-mainloop: BM*H (spans As+Bs)

    int tid = threadIdx.x, lane = tid & 31, warp = tid >> 5;
    int wm = warp & 3;        // 0..3 : 32 rows each
    int wn = warp >> 2;       // 0..3 : H/4 cols each

    if (tid < BM) {
        int idx = base + tid;
        if (idx >= count) idx = count - 1;
        sRow[tid] = perm[idx];
    }
    for (int i = tid; i < H * H2; i += NTHREADS) {
        int k = i / H2, n = i - k * H2;
        sW2[k * H2 + (n ^ ((k & 3) << 3))] = __uint_as_float(f2tf(W2[i]));
    }
    if (tid < H2) { sW3[tid] = W3[tid]; sB2[tid] = b2[tid]; }
    __syncthreads();

    // gather rows for A-loader slots (128x32 floats = 1024 float4, 512 thr -> 2 its)
    int rid[2];
#pragma unroll
    for (int it = 0; it < 2; it++) rid[it] = sRow[(tid + it * NTHREADS) >> 3];

    float acc[2][JB][4];
#pragma unroll
    for (int i = 0; i < 2; i++)
#pragma unroll
        for (int j = 0; j < JB; j++)
#pragma unroll
            for (int r = 0; r < 4; r++) acc[i][j][r] = 0.f;

    auto loadA = [&](int buf, int kt) {
        float* dst = As + buf * BM * BK;
#pragma unroll
        for (int it = 0; it < 2; it++) {
            int slot = tid + it * NTHREADS;
            int r  = slot >> 3;
            int c4 = (slot & 7) << 2;
            int pc = c4 ^ ((r & 7) << 2);
            cp16(dst + r * BK + pc, X + (size_t)rid[it] * KDIM + kt * BK + c4);
        }
    };
    auto loadB = [&](int buf, int kt) {
        float* dst = Bs + buf * BK * H;
        const float* src = W1 + (size_t)kt * BK * H;
#pragma unroll
        for (int it = 0; it < (8 * H) / NTHREADS; it++) {
            int slot = tid + it * NTHREADS;
            int r  = slot / (H / 4);
            int c4 = (slot % (H / 4)) << 2;
            int pc = c4 ^ ((r & 3) << 3);
            cp16(dst + r * H + pc, src + r * H + c4);
        }
    };

    // 3-stage pipeline
    loadA(0, 0); loadB(0, 0);
    asm volatile("cp.async.commit_group;\n");
    loadA(1, 1); loadB(1, 1);
    asm volatile("cp.async.commit_group;\n");

    for (int kt = 0; kt < NKT; kt++) {
        int buf = kt % 3;
        if (kt + 2 < NKT) {
            int nb = (kt + 2) % 3;
            loadA(nb, kt + 2);
            loadB(nb, kt + 2);
            asm volatile("cp.async.commit_group;\n");
            asm volatile("cp.async.wait_group 2;\n");
        } else if (kt + 1 < NKT) {
            asm volatile("cp.async.wait_group 1;\n");
        } else {
            asm volatile("cp.async.wait_group 0;\n");
        }
        __syncthreads();

        const float* A0 = As + buf * BM * BK;
        const float* B0 = Bs + buf * BK * H;

#pragma unroll
        for (int ks = 0; ks < 4; ks++) {
            uint32_t afr[2][4];
#pragma unroll
            for (int i = 0; i < 2; i++) {
                int row  = wm * 32 + i * 16 + (lane >> 2);
                int row8 = row + 8;
                int c0 = ks * 8 + (lane & 3);
                int c1 = c0 + 4;
                afr[i][0] = f2tf(A0[row  * BK + (c0 ^ ((row  & 7) << 2))]);
                afr[i][1] = f2tf(A0[row8 * BK + (c0 ^ ((row8 & 7) << 2))]);
                afr[i][2] = f2tf(A0[row  * BK + (c1 ^ ((row  & 7) << 2))]);
                afr[i][3] = f2tf(A0[row8 * BK + (c1 ^ ((row8 & 7) << 2))]);
            }
            uint32_t bfr[JB][2];
#pragma unroll
            for (int j = 0; j < JB; j++) {
                int n  = wn * (H / 4) + j * 8 + (lane >> 2);
                int k0 = ks * 8 + (lane & 3);
                int k1 = k0 + 4;
                bfr[j][0] = __float_as_uint(B0[k0 * H + (n ^ ((k0 & 3) << 3))]);
                bfr[j][1] = __float_as_uint(B0[k1 * H + (n ^ ((k1 & 3) << 3))]);
            }
#pragma unroll
            for (int i = 0; i < 2; i++)
#pragma unroll
                for (int j = 0; j < JB; j++) {
                    asm volatile(
                        "mma.sync.aligned.m16n8k8.row.col.f32.tf32.tf32.f32 "
                        "{%0,%1,%2,%3}, {%4,%5,%6,%7}, {%8,%9}, {%0,%1,%2,%3};\n"
                        : "+f"(acc[i][j][0]), "+f"(acc[i][j][1]),
                          "+f"(acc[i][j][2]), "+f"(acc[i][j][3])
                        : "r"(afr[i][0]), "r"(afr[i][1]), "r"(afr[i][2]), "r"(afr[i][3]),
                          "r"(bfr[j][0]), "r"(bfr[j][1]));
                }
        }
        __syncthreads();
    }

    // ---- layer-1 epilogue: +b1, relu, tf32-round, store h1 (swizzled) ----
#pragma unroll
    for (int i = 0; i < 2; i++) {
        int row0 = wm * 32 + i * 16 + (lane >> 2);
        int row1 = row0 + 8;
#pragma unroll
        for (int j = 0; j < JB; j++) {
            int col = wn * (H / 4) + j * 8 + 2 * (lane & 3);
            float bv0 = b1[col], bv1 = b1[col + 1];
            h1[row0 * H + ((col)     ^ ((row0 & 7) << 2))] =
                __uint_as_float(f2tf(fmaxf(acc[i][j][0] + bv0, 0.f)));
            h1[row0 * H + ((col + 1) ^ ((row0 & 7) << 2))] =
                __uint_as_float(f2tf(fmaxf(acc[i][j][1] + bv1, 0.f)));
            h1[row1 * H + ((col)     ^ ((row1 & 7) << 2))] =
                __uint_as_float(f2tf(fmaxf(acc[i][j][2] + bv0, 0.f)));
            h1[row1 * H + ((col + 1) ^ ((row1 & 7) << 2))] =
                __uint_as_float(f2tf(fmaxf(acc[i][j][3] + bv1, 0.f)));
        }
    }
    __syncthreads();
    if (tid < BM) sPart[tid] = 0.f;

    // ---- layer 2: acc2 = h1 @ W2 (tf32 mma; operands pre-rounded) ----
    float acc2[2][JB2][4];
#pragma unroll
    for (int i = 0; i < 2; i++)
#pragma unroll
        for (int j = 0; j < JB2; j++)
#pragma unroll
            for (int r = 0; r < 4; r++) acc2[i][j][r] = 0.f;

#pragma unroll
    for (int ks = 0; ks < H / 8; ks++) {
        uint32_t afr[2][4];
#pragma unroll
        for (int i = 0; i < 2; i++) {
            int row  = wm * 32 + i * 16 + (lane >> 2);
            int row8 = row + 8;
            int c0 = ks * 8 + (lane & 3);
            int c1 = c0 + 4;
            afr[i][0] = __float_as_uint(h1[row  * H + (c0 ^ ((row  & 7) << 2))]);
            afr[i][1] = __float_as_uint(h1[row8 * H + (c0 ^ ((row8 & 7) << 2))]);
            afr[i][2] = __float_as_uint(h1[row  * H + (c1 ^ ((row  & 7) << 2))]);
            afr[i][3] = __float_as_uint(h1[row8 * H + (c1 ^ ((row8 & 7) << 2))]);
        }
        uint32_t bfr[JB2][2];
#pragma unroll
        for (int j = 0; j < JB2; j++) {
            int n  = wn * (H2 / 4) + j * 8 + (lane >> 2);
            int k0 = ks * 8 + (lane & 3);
            int k1 = k0 + 4;
            bfr[j][0] = __float_as_uint(sW2[k0 * H2 + (n ^ ((k0 & 3) << 3))]);
            bfr[j][1] = __float_as_uint(sW2[k1 * H2 + (n ^ ((k1 & 3) << 3))]);
        }
#pragma unroll
        for (int i = 0; i < 2; i++)
#pragma unroll
            for (int j = 0; j < JB2; j++) {
                asm volatile(
                    "mma.sync.aligned.m16n8k8.row.col.f32.tf32.tf32.f32 "
                    "{%0,%1,%2,%3}, {%4,%5,%6,%7}, {%8,%9}, {%0,%1,%2,%3};\n"
                    : "+f"(acc2[i][j][0]), "+f"(acc2[i][j][1]),
                      "+f"(acc2[i][j][2]), "+f"(acc2[i][j][3])
                    : "r"(afr[i][0]), "r"(afr[i][1]), "r"(afr[i][2]), "r"(afr[i][3]),
                      "r"(bfr[j][0]), "r"(bfr[j][1]));
            }
    }

    // ---- layer 3: +b2, relu, dot W3, warp-reduce, cross-warp atomic, scatter ----
    float p[4] = {0.f, 0.f, 0.f, 0.f};
#pragma unroll
    for (int i = 0; i < 2; i++)
#pragma unroll
        for (int j = 0; j < JB2; j++) {
            int col = wn * (H2 / 4) + j * 8 + 2 * (lane & 3);
            float w0 = sW3[col], w1 = sW3[col + 1];
            float c0 = sB2[col], c1 = sB2[col + 1];
            p[i * 2 + 0] += fmaxf(acc2[i][j][0] + c0, 0.f) * w0
                          + fmaxf(acc2[i][j][1] + c1, 0.f) * w1;
            p[i * 2 + 1] += fmaxf(acc2[i][j][2] + c0, 0.f) * w0
                          + fmaxf(acc2[i][j][3] + c1, 0.f) * w1;
        }
#pragma unroll
    for (int t = 0; t < 4; t++) {
        p[t] += __shfl_xor_sync(0xffffffffu, p[t], 1);
        p[t] += __shfl_xor_sync(0xffffffffu, p[t], 2);
    }
    __syncthreads();   // sPart zero visible, all lanes done
    if ((lane & 3) == 0) {
#pragma unroll
        for (int i = 0; i < 2; i++)
#pragma unroll
            for (int hh = 0; hh < 2; hh++) {
                int m = wm * 32 + i * 16 + hh * 8 + (lane >> 2);
                atomicAdd(&sPart[m], p[i * 2 + hh]);
            }
    }
    __syncthreads();
    if (tid < BM && base + tid < count)
        out[sRow[tid]] = sPart[tid] + b3[0];
}

// ---------------- fused kernel: all 4 experts in one launch ----------------
__global__ __launch_bounds__(NTHREADS) void fused_kernel(
    const float* __restrict__ X,
    const float* __restrict__ b1_sc, const float* __restrict__ W2_sc,
    const float* __restrict__ b2_sc, const float* __restrict__ W3_sc,
    const float* __restrict__ b3_sc,
    const float* __restrict__ b1_st, const float* __restrict__ W2_st,
    const float* __restrict__ b2_st, const float* __restrict__ W3_st,
    const float* __restrict__ b3_st,
    const float* __restrict__ b1_wm, const float* __restrict__ W2_wm,
    const float* __restrict__ b2_wm, const float* __restrict__ W3_wm,
    const float* __restrict__ b3_wm,
    const float* __restrict__ b1_ch, const float* __restrict__ W2_ch,
    const float* __restrict__ b2_ch, const float* __restrict__ W3_ch,
    const float* __restrict__ b3_ch,
    float* __restrict__ out)
{
    extern __shared__ float smem[];
    int e = blockIdx.x & 3;        // interleave experts for load balance
    int chunk = blockIdx.x >> 2;
    if (e == 0)
        expert_body<64>(0, chunk, X, g_W1tf + W1OFF_SC,
                        b1_sc, W2_sc, b2_sc, W3_sc, b3_sc, out, smem);
    else if (e == 1)
        expert_body<64>(1, chunk, X, g_W1tf + W1OFF_ST,
                        b1_st, W2_st, b2_st, W3_st, b3_st, out, smem);
    else if (e == 2)
        expert_body<128>(2, chunk, X, g_W1tf + W1OFF_WM,
                         b1_wm, W2_wm, b2_wm, W3_wm, b3_wm, out, smem);
    else
        expert_body<128>(3, chunk, X, g_W1tf + W1OFF_CH,
                         b1_ch, W2_ch, b2_ch, W3_ch, b3_ch, out, smem);
}

// ---------------- launch ----------------
extern "C" void kernel_launch(void* const* d_in, const int* in_sizes, int n_in,
                              void* d_out, int out_size) {
    const float* x      = (const float*)d_in[0];
    const int*   labels = (const int*)d_in[1];
    const float* W1_sc = (const float*)d_in[2],  *b1_sc = (const float*)d_in[3];
    const float* W2_sc = (const float*)d_in[4],  *b2_sc = (const float*)d_in[5];
    const float* W3_sc = (const float*)d_in[6],  *b3_sc = (const float*)d_in[7];
    const float* W1_st = (const float*)d_in[8],  *b1_st = (const float*)d_in[9];
    const float* W2_st = (const float*)d_in[10], *b2_st = (const float*)d_in[11];
    const float* W3_st = (const float*)d_in[12], *b3_st = (const float*)d_in[13];
    const float* W1_wm = (const float*)d_in[14], *b1_wm = (const float*)d_in[15];
    const float* W2_wm = (const float*)d_in[16], *b2_wm = (const float*)d_in[17];
    const float* W3_wm = (const float*)d_in[18], *b3_wm = (const float*)d_in[19];
    const float* W1_ch = (const float*)d_in[20], *b1_ch = (const float*)d_in[21];
    const float* W2_ch = (const float*)d_in[22], *b2_ch = (const float*)d_in[23];
    const float* W3_ch = (const float*)d_in[24], *b3_ch = (const float*)d_in[25];
    float* out = (float*)d_out;

    zero_cnt_kernel<<<1, 32>>>();
    bucket_kernel<<<NROWS / 256, 256>>>(labels, out);
    prep_kernel<<<768, 256>>>(W1_sc, W1_st, W1_wm, W1_ch);

    // smem (floats), H=128 layout is max:
    // 12288 (A x3) + 12288 (B x3) + 8192 (W2) + 64 + 64 + 128 + 128 = 33152 -> 132608 B
    const size_t smem_max = 33152 * sizeof(float);
    cudaFuncSetAttribute(fused_kernel, cudaFuncAttributeMaxDynamicSharedMemorySize,
                         (int)smem_max);

    fused_kernel<<<4 * (NROWS / BM), NTHREADS, smem_max>>>(x,
        b1_sc, W2_sc, b2_sc, W3_sc, b3_sc,
        b1_st, W2_st, b2_st, W3_st, b3_st,
        b1_wm, W2_wm, b2_wm, W3_wm, b3_wm,
        b1_ch, W2_ch, b2_ch, W3_ch, b3_ch,
        out);
}

// round 7
// speedup vs baseline: 1.2374x; 1.1214x over previous
#include <cuda_runtime.h>
#include <stdint.h>

#define NROWS 65536
#define KDIM  2048
#define BM 128
#define BK 32
#define NKT (KDIM / BK)   // 64
#define NT  256

// ---------------- device scratch ----------------
__device__ int g_cnt[4];
__device__ int g_perm[4][NROWS];          // 1 MB
__device__ float g_W1tf[KDIM * 384];      // 3 MB: sc|st|wm|ch (K-major [k][n]), tf32-rounded
__device__ float g_W2tf[20480];           // W2 all experts, tf32-rounded

#define W1OFF_SC 0
#define W1OFF_ST (KDIM * 64)
#define W1OFF_WM (KDIM * 128)
#define W1OFF_CH (KDIM * 256)
#define W2OFF_SC 0
#define W2OFF_ST 2048
#define W2OFF_WM 4096
#define W2OFF_CH 12288

// ---------------- helpers ----------------
__device__ __forceinline__ void cp16(float* dst, const float* src) {
    uint32_t d = (uint32_t)__cvta_generic_to_shared(dst);
    asm volatile("cp.async.ca.shared.global [%0], [%1], 16;\n" :: "r"(d), "l"(src));
}
__device__ __forceinline__ uint32_t f2tf(float x) {
    uint32_t u; asm("cvt.rna.tf32.f32 %0, %1;" : "=r"(u) : "f"(x)); return u;
}

// ---------------- prep: tf32-round W1 (K-major concat) + W2 ----------------
__global__ void prep_kernel(const float* __restrict__ W1_sc, const float* __restrict__ W1_st,
                            const float* __restrict__ W1_wm, const float* __restrict__ W1_ch,
                            const float* __restrict__ W2_sc, const float* __restrict__ W2_st,
                            const float* __restrict__ W2_wm, const float* __restrict__ W2_ch) {
    const int T = KDIM * 384;
    for (int i = blockIdx.x * blockDim.x + threadIdx.x; i < T;
         i += gridDim.x * blockDim.x) {
        float v;
        if (i < W1OFF_ST)      v = W1_sc[i];
        else if (i < W1OFF_WM) v = W1_st[i - W1OFF_ST];
        else if (i < W1OFF_CH) v = W1_wm[i - W1OFF_WM];
        else                   v = W1_ch[i - W1OFF_CH];
        g_W1tf[i] = __uint_as_float(f2tf(v));
    }
    // W2: 20480 floats
    for (int i = blockIdx.x * blockDim.x + threadIdx.x; i < 20480;
         i += gridDim.x * blockDim.x) {
        float v;
        if (i < W2OFF_ST)      v = W2_sc[i];
        else if (i < W2OFF_WM) v = W2_st[i - W2OFF_ST];
        else if (i < W2OFF_CH) v = W2_wm[i - W2OFF_WM];
        else                   v = W2_ch[i - W2OFF_CH];
        g_W2tf[i] = __uint_as_float(f2tf(v));
    }
}

// ---------------- bucket kernels ----------------
__global__ void zero_cnt_kernel() {
    if (threadIdx.x < 4) g_cnt[threadIdx.x] = 0;
}

__global__ void bucket_kernel(const int* __restrict__ labels, float* __restrict__ out) {
    int r = blockIdx.x * blockDim.x + threadIdx.x;
    if (r >= NROWS) return;
    int lab = labels[r];
    bool valid = (lab >= 0) && (lab <= 3);
    if (!valid) { out[r] = 0.f; lab = -1; }
    int lane = threadIdx.x & 31;
#pragma unroll
    for (int l = 0; l < 4; l++) {
        unsigned mask = __ballot_sync(0xffffffffu, lab == l);
        if (lab == l) {
            int leader = __ffs(mask) - 1;
            int myrank = __popc(mask & ((1u << lane) - 1));
            int basep = 0;
            if (lane == leader) basep = atomicAdd(&g_cnt[l], __popc(mask));
            basep = __shfl_sync(mask, basep, leader);
            g_perm[l][basep + myrank] = r;
        }
    }
}

// ---------------- smem layout (floats), H=128 worst case ----------------
// A stages:  [0, 12288)       3 x 128x32
// B stages:  [12288, 24576)   3 x 32xH (H=128: full; H=64: first half)
// sW2:       [24576, 32768)   H x H2
// sW3 @32768 (64) | sB2 @32832 (64) | sPart @32896 (128) | sRow @33024 (128 int)
#define OFF_B    12288
#define OFF_W2   24576
#define OFF_TAIL 32768
#define SMEM_FLOATS 33152

// ---------------- fused expert body (256 thr, 8 warps = 4m x 2n) ----------------
template<int H>
__device__ __forceinline__ void expert_body(
    int e, int chunk, const float* __restrict__ X,
    const float* __restrict__ W1,   // tf32-rounded [KDIM][H]
    const float* __restrict__ W2,   // tf32-rounded [H][H2]
    const float* __restrict__ b1, const float* __restrict__ b2,
    const float* __restrict__ W3, const float* __restrict__ b3,
    float* __restrict__ out, float* smem)
{
    constexpr int H2   = H / 2;
    constexpr int JB   = H / 16;     // layer-1 n8 blocks/warp (warp n-tile H/2)
    constexpr int JB2  = H2 / 16;    // layer-2 n8 blocks/warp
    constexpr int ABUF = BM * BK;    // 4096
    constexpr int BBUF = BK * H;     // 4096 / 2048

    int count = g_cnt[e];
    int base = chunk * BM;
    if (base >= count) return;
    const int* perm = g_perm[e];

    float* As    = smem;
    float* Bs    = smem + OFF_B;
    float* sW2   = smem + OFF_W2;
    float* sW3   = smem + OFF_TAIL;
    float* sB2   = smem + OFF_TAIL + 64;
    float* sPart = smem + OFF_TAIL + 128;
    int*   sRow  = (int*)(smem + OFF_TAIL + 256);
    float* h1    = As;               // reused post-mainloop: BM*H floats

    int tid = threadIdx.x, lane = tid & 31, warp = tid >> 5;
    int wm = warp & 3;        // 32 rows each
    int wn = warp >> 2;       // 0..1, H/2 cols each

    if (tid < BM) {
        int idx = base + tid;
        if (idx >= count) idx = count - 1;
        sRow[tid] = perm[idx];
    }
    if (tid < H2) { sW3[tid] = W3[tid]; sB2[tid] = b2[tid]; }
    __syncthreads();

    int rid[4];
#pragma unroll
    for (int it = 0; it < 4; it++) rid[it] = sRow[(tid + it * NT) >> 3];

    float acc[2][JB][4];
#pragma unroll
    for (int i = 0; i < 2; i++)
#pragma unroll
        for (int j = 0; j < JB; j++)
#pragma unroll
            for (int r = 0; r < 4; r++) acc[i][j][r] = 0.f;

    auto loadA = [&](int buf, int kt) {
        float* dst = As + buf * ABUF;
#pragma unroll
        for (int it = 0; it < 4; it++) {
            int slot = tid + it * NT;
            int r  = slot >> 3;
            int c4 = (slot & 7) << 2;
            int pc = c4 ^ ((r & 7) << 2);
            cp16(dst + r * BK + pc, X + (size_t)rid[it] * KDIM + kt * BK + c4);
        }
    };
    auto loadB = [&](int buf, int kt) {
        float* dst = Bs + buf * BBUF;
        const float* src = W1 + (size_t)kt * BK * H;
#pragma unroll
        for (int it = 0; it < (BK * H) / (4 * NT); it++) {
            int slot = tid + it * NT;
            int r  = slot / (H / 4);
            int c4 = (slot % (H / 4)) << 2;
            int pc = c4 ^ ((r & 3) << 3);
            cp16(dst + r * H + pc, src + r * H + c4);
        }
    };
    auto loadW2 = [&]() {
#pragma unroll
        for (int it = 0; it < (H * H2) / (4 * NT); it++) {
            int slot = tid + it * NT;
            int r  = slot / (H2 / 4);
            int c4 = (slot % (H2 / 4)) << 2;
            int pc = c4 ^ ((r & 3) << 3);
            cp16(sW2 + r * H2 + pc, W2 + r * H2 + c4);
        }
    };

    // 3-stage pipeline prologue
    loadA(0, 0); loadB(0, 0);
    asm volatile("cp.async.commit_group;\n");
    loadA(1, 1); loadB(1, 1);
    asm volatile("cp.async.commit_group;\n");

    for (int kt = 0; kt < NKT; kt++) {
        int buf = kt % 3;
        if (kt + 2 < NKT) {
            int nb = (kt + 2) % 3;
            loadA(nb, kt + 2);
            loadB(nb, kt + 2);
            asm volatile("cp.async.commit_group;\n");
            asm volatile("cp.async.wait_group 2;\n");
        } else if (kt + 1 < NKT) {
            loadW2();                                  // prefetch layer-2 weights
            asm volatile("cp.async.commit_group;\n");
            asm volatile("cp.async.wait_group 2;\n");
        } else {
            asm volatile("cp.async.wait_group 1;\n");  // W2 may still be in flight
        }
        __syncthreads();

        const float* A0 = As + buf * ABUF;
        const float* B0 = Bs + buf * BBUF;

#pragma unroll
        for (int ks = 0; ks < 4; ks++) {
            uint32_t afr[2][4];
#pragma unroll
            for (int i = 0; i < 2; i++) {
                int row  = wm * 32 + i * 16 + (lane >> 2);
                int row8 = row + 8;
                int c0 = ks * 8 + (lane & 3);
                int c1 = c0 + 4;
                afr[i][0] = f2tf(A0[row  * BK + (c0 ^ ((row  & 7) << 2))]);
                afr[i][1] = f2tf(A0[row8 * BK + (c0 ^ ((row8 & 7) << 2))]);
                afr[i][2] = f2tf(A0[row  * BK + (c1 ^ ((row  & 7) << 2))]);
                afr[i][3] = f2tf(A0[row8 * BK + (c1 ^ ((row8 & 7) << 2))]);
            }
            uint32_t bfr[JB][2];
#pragma unroll
            for (int j = 0; j < JB; j++) {
                int n  = wn * (H / 2) + j * 8 + (lane >> 2);
                int k0 = ks * 8 + (lane & 3);
                int k1 = k0 + 4;
                bfr[j][0] = __float_as_uint(B0[k0 * H + (n ^ ((k0 & 3) << 3))]);
                bfr[j][1] = __float_as_uint(B0[k1 * H + (n ^ ((k1 & 3) << 3))]);
            }
#pragma unroll
            for (int i = 0; i < 2; i++)
#pragma unroll
                for (int j = 0; j < JB; j++) {
                    asm volatile(
                        "mma.sync.aligned.m16n8k8.row.col.f32.tf32.tf32.f32 "
                        "{%0,%1,%2,%3}, {%4,%5,%6,%7}, {%8,%9}, {%0,%1,%2,%3};\n"
                        : "+f"(acc[i][j][0]), "+f"(acc[i][j][1]),
                          "+f"(acc[i][j][2]), "+f"(acc[i][j][3])
                        : "r"(afr[i][0]), "r"(afr[i][1]), "r"(afr[i][2]), "r"(afr[i][3]),
                          "r"(bfr[j][0]), "r"(bfr[j][1]));
                }
        }
        __syncthreads();
    }

    // ---- layer-1 epilogue: +b1, relu, tf32-round, store h1 (swizzled) ----
#pragma unroll
    for (int i = 0; i < 2; i++) {
        int row0 = wm * 32 + i * 16 + (lane >> 2);
        int row1 = row0 + 8;
#pragma unroll
        for (int j = 0; j < JB; j++) {
            int col = wn * (H / 2) + j * 8 + 2 * (lane & 3);
            float bv0 = b1[col], bv1 = b1[col + 1];
            float2 v0, v1;
            v0.x = __uint_as_float(f2tf(fmaxf(acc[i][j][0] + bv0, 0.f)));
            v0.y = __uint_as_float(f2tf(fmaxf(acc[i][j][1] + bv1, 0.f)));
            v1.x = __uint_as_float(f2tf(fmaxf(acc[i][j][2] + bv0, 0.f)));
            v1.y = __uint_as_float(f2tf(fmaxf(acc[i][j][3] + bv1, 0.f)));
            *(float2*)&h1[row0 * H + (col ^ ((row0 & 7) << 2))] = v0;
            *(float2*)&h1[row1 * H + (col ^ ((row1 & 7) << 2))] = v1;
        }
    }
    asm volatile("cp.async.wait_group 0;\n");   // sW2 landed
    __syncthreads();

    // ---- layer 2: acc2 = h1 @ W2 (tf32 mma; operands pre-rounded) ----
    float acc2[2][JB2][4];
#pragma unroll
    for (int i = 0; i < 2; i++)
#pragma unroll
        for (int j = 0; j < JB2; j++)
#pragma unroll
            for (int r = 0; r < 4; r++) acc2[i][j][r] = 0.f;

#pragma unroll
    for (int ks = 0; ks < H / 8; ks++) {
        uint32_t afr[2][4];
#pragma unroll
        for (int i = 0; i < 2; i++) {
            int row  = wm * 32 + i * 16 + (lane >> 2);
            int row8 = row + 8;
            int c0 = ks * 8 + (lane & 3);
            int c1 = c0 + 4;
            afr[i][0] = __float_as_uint(h1[row  * H + (c0 ^ ((row  & 7) << 2))]);
            afr[i][1] = __float_as_uint(h1[row8 * H + (c0 ^ ((row8 & 7) << 2))]);
            afr[i][2] = __float_as_uint(h1[row  * H + (c1 ^ ((row  & 7) << 2))]);
            afr[i][3] = __float_as_uint(h1[row8 * H + (c1 ^ ((row8 & 7) << 2))]);
        }
        uint32_t bfr[JB2][2];
#pragma unroll
        for (int j = 0; j < JB2; j++) {
            int n  = wn * (H2 / 2) + j * 8 + (lane >> 2);
            int k0 = ks * 8 + (lane & 3);
            int k1 = k0 + 4;
            bfr[j][0] = __float_as_uint(sW2[k0 * H2 + (n ^ ((k0 & 3) << 3))]);
            bfr[j][1] = __float_as_uint(sW2[k1 * H2 + (n ^ ((k1 & 3) << 3))]);
        }
#pragma unroll
        for (int i = 0; i < 2; i++)
#pragma unroll
            for (int j = 0; j < JB2; j++) {
                asm volatile(
                    "mma.sync.aligned.m16n8k8.row.col.f32.tf32.tf32.f32 "
                    "{%0,%1,%2,%3}, {%4,%5,%6,%7}, {%8,%9}, {%0,%1,%2,%3};\n"
                    : "+f"(acc2[i][j][0]), "+f"(acc2[i][j][1]),
                      "+f"(acc2[i][j][2]), "+f"(acc2[i][j][3])
                    : "r"(afr[i][0]), "r"(afr[i][1]), "r"(afr[i][2]), "r"(afr[i][3]),
                      "r"(bfr[j][0]), "r"(bfr[j][1]));
            }
    }

    // ---- layer 3: +b2, relu, dot W3, reduce, +b3, scatter ----
    float p[4] = {0.f, 0.f, 0.f, 0.f};
#pragma unroll
    for (int i = 0; i < 2; i++)
#pragma unroll
        for (int j = 0; j < JB2; j++) {
            int col = wn * (H2 / 2) + j * 8 + 2 * (lane & 3);
            float w0 = sW3[col], w1 = sW3[col + 1];
            float c0 = sB2[col], c1 = sB2[col + 1];
            p[i * 2 + 0] += fmaxf(acc2[i][j][0] + c0, 0.f) * w0
                          + fmaxf(acc2[i][j][1] + c1, 0.f) * w1;
            p[i * 2 + 1] += fmaxf(acc2[i][j][2] + c0, 0.f) * w0
                          + fmaxf(acc2[i][j][3] + c1, 0.f) * w1;
        }
#pragma unroll
    for (int t = 0; t < 4; t++) {
        p[t] += __shfl_xor_sync(0xffffffffu, p[t], 1);
        p[t] += __shfl_xor_sync(0xffffffffu, p[t], 2);
    }
    if (wn == 0 && (lane & 3) == 0) {
#pragma unroll
        for (int i = 0; i < 2; i++)
#pragma unroll
            for (int hh = 0; hh < 2; hh++) {
                int m = wm * 32 + i * 16 + hh * 8 + (lane >> 2);
                sPart[m] = p[i * 2 + hh];
            }
    }
    __syncthreads();
    if (wn == 1 && (lane & 3) == 0) {
        float b3v = b3[0];
#pragma unroll
        for (int i = 0; i < 2; i++)
#pragma unroll
            for (int hh = 0; hh < 2; hh++) {
                int m = wm * 32 + i * 16 + hh * 8 + (lane >> 2);
                if (base + m < count)
                    out[sRow[m]] = sPart[m] + p[i * 2 + hh] + b3v;
            }
    }
}

// ---------------- fused kernel: all 4 experts, one launch ----------------
__global__ __launch_bounds__(NT) void fused_kernel(
    const float* __restrict__ X,
    const float* __restrict__ b1_sc, const float* __restrict__ b2_sc,
    const float* __restrict__ W3_sc, const float* __restrict__ b3_sc,
    const float* __restrict__ b1_st, const float* __restrict__ b2_st,
    const float* __restrict__ W3_st, const float* __restrict__ b3_st,
    const float* __restrict__ b1_wm, const float* __restrict__ b2_wm,
    const float* __restrict__ W3_wm, const float* __restrict__ b3_wm,
    const float* __restrict__ b1_ch, const float* __restrict__ b2_ch,
    const float* __restrict__ W3_ch, const float* __restrict__ b3_ch,
    float* __restrict__ out)
{
    extern __shared__ float smem[];
    int e = blockIdx.x & 3;
    int chunk = blockIdx.x >> 2;
    if (e == 0)
        expert_body<64>(0, chunk, X, g_W1tf + W1OFF_SC, g_W2tf + W2OFF_SC,
                        b1_sc, b2_sc, W3_sc, b3_sc, out, smem);
    else if (e == 1)
        expert_body<64>(1, chunk, X, g_W1tf + W1OFF_ST, g_W2tf + W2OFF_ST,
                        b1_st, b2_st, W3_st, b3_st, out, smem);
    else if (e == 2)
        expert_body<128>(2, chunk, X, g_W1tf + W1OFF_WM, g_W2tf + W2OFF_WM,
                         b1_wm, b2_wm, W3_wm, b3_wm, out, smem);
    else
        expert_body<128>(3, chunk, X, g_W1tf + W1OFF_CH, g_W2tf + W2OFF_CH,
                         b1_ch, b2_ch, W3_ch, b3_ch, out, smem);
}

// ---------------- launch ----------------
extern "C" void kernel_launch(void* const* d_in, const int* in_sizes, int n_in,
                              void* d_out, int out_size) {
    const float* x      = (const float*)d_in[0];
    const int*   labels = (const int*)d_in[1];
    const float* W1_sc = (const float*)d_in[2],  *b1_sc = (const float*)d_in[3];
    const float* W2_sc = (const float*)d_in[4],  *b2_sc = (const float*)d_in[5];
    const float* W3_sc = (const float*)d_in[6],  *b3_sc = (const float*)d_in[7];
    const float* W1_st = (const float*)d_in[8],  *b1_st = (const float*)d_in[9];
    const float* W2_st = (const float*)d_in[10], *b2_st = (const float*)d_in[11];
    const float* W3_st = (const float*)d_in[12], *b3_st = (const float*)d_in[13];
    const float* W1_wm = (const float*)d_in[14], *b1_wm = (const float*)d_in[15];
    const float* W2_wm = (const float*)d_in[16], *b2_wm = (const float*)d_in[17];
    const float* W3_wm = (const float*)d_in[18], *b3_wm = (const float*)d_in[19];
    const float* W1_ch = (const float*)d_in[20], *b1_ch = (const float*)d_in[21];
    const float* W2_ch = (const float*)d_in[22], *b2_ch = (const float*)d_in[23];
    const float* W3_ch = (const float*)d_in[24], *b3_ch = (const float*)d_in[25];
    float* out = (float*)d_out;

    zero_cnt_kernel<<<1, 32>>>();
    bucket_kernel<<<NROWS / 256, 256>>>(labels, out);
    prep_kernel<<<768, 256>>>(W1_sc, W1_st, W1_wm, W1_ch,
                              W2_sc, W2_st, W2_wm, W2_ch);

    const size_t smem_bytes = (size_t)SMEM_FLOATS * sizeof(float);  // 132,608 B
    cudaFuncSetAttribute(fused_kernel, cudaFuncAttributeMaxDynamicSharedMemorySize,
                         (int)smem_bytes);

    fused_kernel<<<4 * (NROWS / BM), NT, smem_bytes>>>(x,
        b1_sc, b2_sc, W3_sc, b3_sc,
        b1_st, b2_st, W3_st, b3_st,
        b1_wm, b2_wm, W3_wm, b3_wm,
        b1_ch, b2_ch, W3_ch, b3_ch,
        out);
}